// round 2
// baseline (speedup 1.0000x reference)
#include <cuda_runtime.h>
#include <cuda_bf16.h>
#include <math.h>

// Problem constants
#define BATCH 2
#define SEQ 1024
#define NTOK (BATCH*SEQ)          // 2048 tokens
#define DIM 1024                   // D
#define HID 2048                   // H
#define NEXP 8                     // E
#define TOPK 2
#define NSLOT (NTOK*TOPK)          // 4096 slots
#define HID2 (2*HID)               // 4096 (gate0 rows then gate1 rows)

// -------- scratch (static __device__; allocation is forbidden) --------
__device__ float g_z[(size_t)NSLOT * HID2];      // 64 MB: pre-activation [slot][4096]
__device__ float g_act[(size_t)NSLOT * HID];     // 32 MB: gated act [slot][2048]
__device__ float g_part[(size_t)NSLOT * DIM];    // 16 MB: per-slot partial out
__device__ float g_linT[(size_t)NEXP * DIM * HID]; // 64 MB: linear_w transposed [E][D][H]
__device__ int   g_cnt[NEXP];
__device__ int   g_tok[NEXP * NTOK];             // A-row gather for up-GEMM (token idx)
__device__ int   g_slot[NEXP * NTOK];            // C-row scatter (slot idx = tok*2+k)
__device__ float g_wt[NEXP * NTOK];              // combine weight per slot

// -------- helpers --------
__device__ __forceinline__ unsigned long long ffma2(unsigned long long a,
                                                    unsigned long long b,
                                                    unsigned long long c) {
    unsigned long long d;
    asm("fma.rn.f32x2 %0, %1, %2, %3;" : "=l"(d) : "l"(a), "l"(b), "l"(c));
    return d;
}
__device__ __forceinline__ float ull_lo(unsigned long long v) { return __uint_as_float((unsigned)v); }
__device__ __forceinline__ float ull_hi(unsigned long long v) { return __uint_as_float((unsigned)(v >> 32)); }

__device__ __forceinline__ float gelu_tanh(float v) {
    float u = 0.7978845608028654f * (v + 0.044715f * v * v * v);
    return 0.5f * v * (1.0f + tanhf(u));
}

// -------- kernel 0: zero per-expert counters (graph replays need this) ----
__global__ void zero_counts_kernel() {
    if (threadIdx.x < NEXP) g_cnt[threadIdx.x] = 0;
}

// -------- kernel T: transpose linear_w [E][H][D] -> g_linT [E][D][H] ------
__global__ void transpose_kernel(const float* __restrict__ lw) {
    __shared__ float tile[32][33];
    int e = blockIdx.z;
    int d0 = blockIdx.x * 32;
    int h0 = blockIdx.y * 32;
    int tx = threadIdx.x, ty = threadIdx.y;   // 32 x 8
    const float* src = lw + (size_t)e * HID * DIM;
    float* dst = g_linT + (size_t)e * DIM * HID;
#pragma unroll
    for (int j = 0; j < 32; j += 8)
        tile[ty + j][tx] = src[(size_t)(h0 + ty + j) * DIM + d0 + tx];
    __syncthreads();
#pragma unroll
    for (int j = 0; j < 32; j += 8)
        dst[(size_t)(d0 + ty + j) * HID + h0 + tx] = tile[tx][ty + j];
}

// -------- kernel R: router (1 block of 256 per token) --------
__global__ void router_kernel(const float* __restrict__ x,
                              const float* __restrict__ rscale,
                              const float* __restrict__ rw,
                              const float* __restrict__ pes) {
    int t = blockIdx.x;
    const float* xr = x + (size_t)t * DIM;
    __shared__ float sx[DIM];
    __shared__ float sred[33];
    __shared__ float slog[NEXP];
    int tid = threadIdx.x;
    int lane = tid & 31;
    int wid = tid >> 5;

    float4 v = ((const float4*)xr)[tid];          // 256*4 = 1024
    ((float4*)sx)[tid] = v;
    float ss = v.x * v.x + v.y * v.y + v.z * v.z + v.w * v.w;
#pragma unroll
    for (int o = 16; o > 0; o >>= 1) ss += __shfl_down_sync(0xffffffffu, ss, o);
    if (lane == 0) sred[wid] = ss;
    __syncthreads();
    if (tid == 0) {
        float tot = 0.f;
#pragma unroll
        for (int i = 0; i < 8; i++) tot += sred[i];
        sred[32] = rsqrtf(tot / (float)DIM + 1e-6f);
    }
    __syncthreads();
    float inv = sred[32] * 0.03125f;  // * rsqrt(D) = 1/32

    // warp e computes logit for expert e
    float acc = 0.f;
    for (int d = lane; d < DIM; d += 32)
        acc += sx[d] * rscale[d] * rw[d * NEXP + wid];
    acc *= inv;
#pragma unroll
    for (int o = 16; o > 0; o >>= 1) acc += __shfl_down_sync(0xffffffffu, acc, o);
    if (lane == 0) slog[wid] = acc;
    __syncthreads();

    if (tid == 0) {
        float lg[NEXP], p[NEXP];
        float mx = -1e30f;
#pragma unroll
        for (int e = 0; e < NEXP; e++) { lg[e] = slog[e]; mx = fmaxf(mx, lg[e]); }
        float psum = 0.f;
#pragma unroll
        for (int e = 0; e < NEXP; e++) { p[e] = expf(lg[e] - mx); psum += p[e]; }
        // top-2 on logits (strict > gives first-index on ties, matching lax.top_k)
        int i1 = 0;
#pragma unroll
        for (int e = 1; e < NEXP; e++) if (lg[e] > lg[i1]) i1 = e;
        int i2 = (i1 == 0) ? 1 : 0;
#pragma unroll
        for (int e = 0; e < NEXP; e++) if (e != i1 && lg[e] > lg[i2]) i2 = e;

        float pr1 = p[i1] / psum, pr2 = p[i2] / psum;
        float rn = pr1 + pr2;
        float w1 = pr1 / rn * pes[i1];
        float w2 = pr2 / rn * pes[i2];

        int pos = atomicAdd(&g_cnt[i1], 1);
        g_tok[i1 * NTOK + pos] = t;
        g_slot[i1 * NTOK + pos] = 2 * t;
        g_wt[i1 * NTOK + pos] = w1;
        pos = atomicAdd(&g_cnt[i2], 1);
        g_tok[i2 * NTOK + pos] = t;
        g_slot[i2 * NTOK + pos] = 2 * t + 1;
        g_wt[i2 * NTOK + pos] = w2;
    }
}

// -------- GEMM: C[m][n] = sum_k A[row(m)][k] * B[e][n][k]  (NT, gathered) --
// MODE 0 (up):   A = x (lda 1024), B = gating_w[e] rows 4096 x 1024, C = g_z
// MODE 1 (down): A = g_act (lda 2048), B = g_linT[e] rows 1024 x 2048,
//                C = g_part, scaled by combine weight
#define BM 64
#define BN 64
#define BKK 32
#define SROW 36   // smem row stride in floats (pad)

template <int MODE>
__global__ __launch_bounds__(256)
void gemm_kernel(const float* __restrict__ Ain, const float* __restrict__ Bin) {
    constexpr int KD  = MODE ? HID : DIM;    // 2048 : 1024
    constexpr int NN  = MODE ? DIM : HID2;   // 1024 : 4096
    constexpr int LDA = MODE ? HID : DIM;
    constexpr int LDC = MODE ? DIM : HID2;

    int e = blockIdx.z;
    int cnt = g_cnt[e];
    int m_base = blockIdx.y * BM;
    if (m_base >= cnt) return;
    int n_base = blockIdx.x * BN;
    (void)NN;

    const int* al = (MODE ? g_slot : g_tok) + e * NTOK;
    const int* cl = g_slot + e * NTOK;
    const float* A = MODE ? g_act : Ain;
    const float* B = (MODE ? g_linT : Bin) + (size_t)e * (size_t)KD * (MODE ? DIM : HID2);
    float* C = MODE ? g_part : g_z;

    __shared__ float As[BM * SROW];
    __shared__ float Bs[BN * SROW];

    int tid = threadIdx.x;
    int nid = tid & 15;           // n sub-lane: cols n_base + nid + 16*j
    int m0  = (tid >> 4) * 4;     // rows m_base + m0 .. m0+3

    unsigned long long acc[4][4];
#pragma unroll
    for (int i = 0; i < 4; i++)
#pragma unroll
        for (int j = 0; j < 4; j++) acc[i][j] = 0ull;

    for (int k0 = 0; k0 < KD; k0 += BKK) {
        // cooperative loads: 512 float4 per tile, 2 per thread
#pragma unroll
        for (int l = 0; l < 2; l++) {
            int idx = tid + l * 256;
            int r = idx >> 3;
            int c = (idx & 7) * 4;
            int row = m_base + r;
            int ar = (row < cnt) ? al[row] : al[0];
            float4 av = *(const float4*)(A + (size_t)ar * LDA + k0 + c);
            *(float4*)&As[r * SROW + c] = av;
            float4 bv = *(const float4*)(B + (size_t)(n_base + r) * KD + k0 + c);
            *(float4*)&Bs[r * SROW + c] = bv;
        }
        __syncthreads();

#pragma unroll
        for (int k4 = 0; k4 < 8; k4++) {
            ulonglong2 av[4], bv[4];
#pragma unroll
            for (int i = 0; i < 4; i++)
                av[i] = *(const ulonglong2*)&As[(m0 + i) * SROW + k4 * 4];
#pragma unroll
            for (int j = 0; j < 4; j++)
                bv[j] = *(const ulonglong2*)&Bs[(nid + j * 16) * SROW + k4 * 4];
#pragma unroll
            for (int i = 0; i < 4; i++)
#pragma unroll
                for (int j = 0; j < 4; j++) {
                    acc[i][j] = ffma2(av[i].x, bv[j].x, acc[i][j]);
                    acc[i][j] = ffma2(av[i].y, bv[j].y, acc[i][j]);
                }
        }
        __syncthreads();
    }

#pragma unroll
    for (int i = 0; i < 4; i++) {
        int row = m_base + m0 + i;
        if (row >= cnt) continue;
        int cr = cl[row];
        float s = MODE ? g_wt[e * NTOK + row] : 1.0f;
        float* Cp = C + (size_t)cr * LDC + n_base + nid;
#pragma unroll
        for (int j = 0; j < 4; j++) {
            float v = ull_lo(acc[i][j]) + ull_hi(acc[i][j]);
            Cp[j * 16] = MODE ? v * s : v;
        }
    }
}

// -------- kernel A: act[s][h] = gelu(z[s][h]) * z[s][2048+h] --------
__global__ void act_kernel() {
    int idx = blockIdx.x * blockDim.x + threadIdx.x;   // float4 index
    if (idx >= NSLOT * HID / 4) return;
    int s = idx >> 9;                 // 2048/4 = 512 float4 per row
    int hc = (idx & 511) * 4;
    const float* zr = g_z + (size_t)s * HID2;
    float4 g = *(const float4*)(zr + hc);
    float4 u = *(const float4*)(zr + HID + hc);
    float4 r;
    r.x = gelu_tanh(g.x) * u.x;
    r.y = gelu_tanh(g.y) * u.y;
    r.z = gelu_tanh(g.z) * u.z;
    r.w = gelu_tanh(g.w) * u.w;
    *(float4*)(g_act + (size_t)s * HID + hc) = r;
}

// -------- kernel C: out[t][d] = part[2t][d] + part[2t+1][d] --------
__global__ void combine_kernel(float* __restrict__ out) {
    int idx = blockIdx.x * blockDim.x + threadIdx.x;   // float4 index
    if (idx >= NTOK * DIM / 4) return;
    int t = idx >> 8;                 // 1024/4 = 256 float4 per row
    int dc = (idx & 255) * 4;
    const float* p = g_part + (size_t)t * 2 * DIM + dc;
    float4 a = *(const float4*)p;
    float4 b = *(const float4*)(p + DIM);
    float4 r;
    r.x = a.x + b.x; r.y = a.y + b.y; r.z = a.z + b.z; r.w = a.w + b.w;
    *(float4*)(out + (size_t)t * DIM + dc) = r;
}

// -------- launcher --------
extern "C" void kernel_launch(void* const* d_in, const int* in_sizes, int n_in,
                              void* d_out, int out_size) {
    const float* x      = (const float*)d_in[0];
    const float* rscale = (const float*)d_in[1];
    const float* rw     = (const float*)d_in[2];
    const float* gw     = (const float*)d_in[3];
    const float* lw     = (const float*)d_in[4];
    const float* pes    = (const float*)d_in[5];
    float* out = (float*)d_out;

    zero_counts_kernel<<<1, 32>>>();
    transpose_kernel<<<dim3(DIM / 32, HID / 32, NEXP), dim3(32, 8)>>>(lw);
    router_kernel<<<NTOK, 256>>>(x, rscale, rw, pes);
    // up: N = 4096 (gate0 rows 0..2047, gate1 rows 2048..4095), K = 1024
    gemm_kernel<0><<<dim3(HID2 / BN, NTOK / BM, NEXP), 256>>>(x, gw);
    act_kernel<<<(NSLOT * HID / 4 + 255) / 256, 256>>>();
    // down: N = 1024, K = 2048, row-scaled by combine weight
    gemm_kernel<1><<<dim3(DIM / BN, NTOK / BM, NEXP), 256>>>(x, gw);
    combine_kernel<<<(NTOK * DIM / 4 + 255) / 256, 256>>>(out);
}

// round 5
// speedup vs baseline: 5.0998x; 5.0998x over previous
#include <cuda_runtime.h>
#include <cuda_bf16.h>
#include <math.h>
#include <stdint.h>

// Problem constants
#define NTOK 2048
#define DIM 1024
#define HID 2048
#define NEXP 8
#define NSLOT 4096

// -------- scratch (static __device__; allocation is forbidden) --------
__device__ float g_act[(size_t)NSLOT * HID];       // 32 MB gated activations
__device__ float g_part[(size_t)NSLOT * DIM];      // 16 MB per-slot partial out
__device__ float g_linT[(size_t)NEXP * DIM * HID]; // 64 MB linear_w^T [E][D][H]
__device__ int   g_cnt[NEXP];
__device__ int   g_tok[NEXP * NTOK];
__device__ int   g_slot[NEXP * NTOK];
__device__ float g_wt[NEXP * NTOK];

// -------- helpers --------
__device__ __forceinline__ float gelu_tanh(float v) {
    float u = 0.7978845608028654f * (v + 0.044715f * v * v * v);
    return 0.5f * v * (1.0f + tanhf(u));
}
__device__ __forceinline__ uint32_t smem_u32(const void* p) {
    uint32_t a;
    asm("{ .reg .u64 t; cvta.to.shared.u64 t, %1; cvt.u32.u64 %0, t; }" : "=r"(a) : "l"(p));
    return a;
}
__device__ __forceinline__ void cp16(uint32_t dst, const void* src) {
    asm volatile("cp.async.cg.shared.global [%0], [%1], 16;" :: "r"(dst), "l"(src));
}
__device__ __forceinline__ uint32_t to_tf32(float f) {
    uint32_t r;
    asm("cvt.rna.tf32.f32 %0, %1;" : "=r"(r) : "f"(f));
    return r;
}
__device__ __forceinline__ void mma_tf32(float& c0, float& c1, float& c2, float& c3,
                                         uint32_t a0, uint32_t a1, uint32_t a2, uint32_t a3,
                                         uint32_t b0, uint32_t b1) {
    asm volatile(
        "mma.sync.aligned.m16n8k8.row.col.f32.tf32.tf32.f32 "
        "{%0,%1,%2,%3}, {%4,%5,%6,%7}, {%8,%9}, {%0,%1,%2,%3};"
        : "+f"(c0), "+f"(c1), "+f"(c2), "+f"(c3)
        : "r"(a0), "r"(a1), "r"(a2), "r"(a3), "r"(b0), "r"(b1));
}

// -------- kernel 0: zero per-expert counters --------
__global__ void zero_counts_kernel() {
    if (threadIdx.x < NEXP) g_cnt[threadIdx.x] = 0;
}

// -------- kernel T: transpose linear_w [E][H][D] -> g_linT [E][D][H] ------
__global__ void transpose_kernel(const float* __restrict__ lw) {
    __shared__ float tile[32][33];
    int e = blockIdx.z;
    int d0 = blockIdx.x * 32;
    int h0 = blockIdx.y * 32;
    int tx = threadIdx.x, ty = threadIdx.y;   // 32 x 8
    const float* src = lw + (size_t)e * HID * DIM;
    float* dst = g_linT + (size_t)e * DIM * HID;
#pragma unroll
    for (int j = 0; j < 32; j += 8)
        tile[ty + j][tx] = src[(size_t)(h0 + ty + j) * DIM + d0 + tx];
    __syncthreads();
#pragma unroll
    for (int j = 0; j < 32; j += 8)
        dst[(size_t)(d0 + ty + j) * HID + h0 + tx] = tile[tx][ty + j];
}

// -------- kernel R: router (1 block of 256 per token) --------
__global__ void router_kernel(const float* __restrict__ x,
                              const float* __restrict__ rscale,
                              const float* __restrict__ rw,
                              const float* __restrict__ pes) {
    int t = blockIdx.x;
    const float* xr = x + (size_t)t * DIM;
    __shared__ float sx[DIM];
    __shared__ float sred[33];
    __shared__ float slog[NEXP];
    int tid = threadIdx.x;
    int lane = tid & 31;
    int wid = tid >> 5;

    float4 v = ((const float4*)xr)[tid];
    ((float4*)sx)[tid] = v;
    float ss = v.x * v.x + v.y * v.y + v.z * v.z + v.w * v.w;
#pragma unroll
    for (int o = 16; o > 0; o >>= 1) ss += __shfl_down_sync(0xffffffffu, ss, o);
    if (lane == 0) sred[wid] = ss;
    __syncthreads();
    if (tid == 0) {
        float tot = 0.f;
#pragma unroll
        for (int i = 0; i < 8; i++) tot += sred[i];
        sred[32] = rsqrtf(tot / (float)DIM + 1e-6f);
    }
    __syncthreads();
    float inv = sred[32] * 0.03125f;

    float acc = 0.f;
    for (int d = lane; d < DIM; d += 32)
        acc += sx[d] * rscale[d] * rw[d * NEXP + wid];
    acc *= inv;
#pragma unroll
    for (int o = 16; o > 0; o >>= 1) acc += __shfl_down_sync(0xffffffffu, acc, o);
    if (lane == 0) slog[wid] = acc;
    __syncthreads();

    if (tid == 0) {
        float lg[NEXP], p[NEXP];
        float mx = -1e30f;
#pragma unroll
        for (int e = 0; e < NEXP; e++) { lg[e] = slog[e]; mx = fmaxf(mx, lg[e]); }
        float psum = 0.f;
#pragma unroll
        for (int e = 0; e < NEXP; e++) { p[e] = expf(lg[e] - mx); psum += p[e]; }
        int i1 = 0;
#pragma unroll
        for (int e = 1; e < NEXP; e++) if (lg[e] > lg[i1]) i1 = e;
        int i2 = (i1 == 0) ? 1 : 0;
#pragma unroll
        for (int e = 0; e < NEXP; e++) if (e != i1 && lg[e] > lg[i2]) i2 = e;

        float pr1 = p[i1] / psum, pr2 = p[i2] / psum;
        float rn = pr1 + pr2;
        float w1 = pr1 / rn * pes[i1];
        float w2 = pr2 / rn * pes[i2];

        int pos = atomicAdd(&g_cnt[i1], 1);
        g_tok[i1 * NTOK + pos] = t;
        g_slot[i1 * NTOK + pos] = 2 * t;
        g_wt[i1 * NTOK + pos] = w1;
        pos = atomicAdd(&g_cnt[i2], 1);
        g_tok[i2 * NTOK + pos] = t;
        g_slot[i2 * NTOK + pos] = 2 * t + 1;
        g_wt[i2 * NTOK + pos] = w2;
    }
}

// ===================== mma.sync tf32 GEMM (compute_103-safe) =====================
// Tile 128x128, BK=32, 8 warps (4m x 2n), warp tile 32x64, m16n8k8 tf32.
// MODE 0 (up):  A = x gathered by g_tok, K=1024. B rows interleaved: smem row r
//   -> gate (r&1), h = bx*64 + (r>>1). Adjacent accumulator cols (2c, 2c+1)
//   are the (z0, z1) pair for the same h -> fused gelu epilogue to g_act.
// MODE 1 (down): A = g_act gathered by g_slot, K=2048. B = g_linT[e] rows
//   bx*128..+128. Epilogue scales by g_wt -> g_part.
#define SROW 36   // smem row stride in floats (16B-aligned, conflict-free frags)
#define ASTG (128 * SROW)

template <int MODE>
__global__ __launch_bounds__(256)
void mma_gemm(const float* __restrict__ Ain, const float* __restrict__ Bin) {
    constexpr int KD  = MODE ? HID : DIM;     // 2048 : 1024
    constexpr int KTC = KD / 32;              // stages

    int e = blockIdx.z;
    int cnt = g_cnt[e];
    int m_base = blockIdx.y * 128;
    if (m_base >= cnt) return;
    int bx = blockIdx.x;

    extern __shared__ float sm[];  // [A s0 | A s1 | B s0 | B s1], ASTG floats each
    uint32_t smb = smem_u32(sm);

    int tid = threadIdx.x;
    int lane = tid & 31;
    int warp = tid >> 5;
    int warp_m = warp >> 1;       // 0..3
    int warp_n = warp & 1;        // 0..1
    int g = lane >> 2;            // 0..7
    int c = lane & 3;             // 0..3

    const int* al = (MODE ? g_slot : g_tok) + e * NTOK;
    const int* cl = g_slot + e * NTOK;
    const float* A = MODE ? g_act : Ain;

    // per-thread cp.async assignments: 4 x 16B chunks per operand per stage
    const float* aptr[4];
    const float* bptr[4];
    uint32_t soff[4];
#pragma unroll
    for (int u = 0; u < 4; u++) {
        int idx = tid + 256 * u;
        int r = idx >> 3, c16 = idx & 7;
        soff[u] = (uint32_t)(r * SROW + c16 * 4) * 4u;
        int mrow = m_base + r;
        int ar = (mrow < cnt) ? al[mrow] : al[0];
        aptr[u] = A + (size_t)ar * KD + c16 * 4;
        if (MODE == 0) {
            int gate = r & 1;
            int h = bx * 64 + (r >> 1);
            bptr[u] = Bin + ((size_t)(e * 2 + gate) * HID + h) * DIM + c16 * 4;
        } else {
            bptr[u] = g_linT + ((size_t)e * DIM + bx * 128 + r) * HID + c16 * 4;
        }
    }

    auto load_stage = [&](int s, int kt) {
        uint32_t sa = smb + (uint32_t)(s * ASTG) * 4u;
        uint32_t sb = smb + (uint32_t)((2 + s) * ASTG) * 4u;
        int k0 = kt * 32;
#pragma unroll
        for (int u = 0; u < 4; u++) {
            cp16(sa + soff[u], aptr[u] + k0);
            cp16(sb + soff[u], bptr[u] + k0);
        }
        asm volatile("cp.async.commit_group;" ::: "memory");
    };

    float acc[2][8][4];
#pragma unroll
    for (int mi = 0; mi < 2; mi++)
#pragma unroll
        for (int nj = 0; nj < 8; nj++)
#pragma unroll
            for (int q = 0; q < 4; q++) acc[mi][nj][q] = 0.f;

    load_stage(0, 0);
    load_stage(1, 1);

    for (int kt = 0; kt < KTC; kt++) {
        int s = kt & 1;
        if (kt >= KTC - 2) asm volatile("cp.async.wait_group 0;" ::: "memory");
        else               asm volatile("cp.async.wait_group 1;" ::: "memory");
        __syncthreads();

        const float* As = sm + s * ASTG;
        const float* Bs = sm + (2 + s) * ASTG;
#pragma unroll
        for (int k8 = 0; k8 < 4; k8++) {
            int kb = k8 * 8;
            uint32_t a[2][4];
#pragma unroll
            for (int mi = 0; mi < 2; mi++) {
                int r0 = warp_m * 32 + mi * 16 + g;
                a[mi][0] = to_tf32(As[r0 * SROW + kb + c]);
                a[mi][1] = to_tf32(As[(r0 + 8) * SROW + kb + c]);
                a[mi][2] = to_tf32(As[r0 * SROW + kb + c + 4]);
                a[mi][3] = to_tf32(As[(r0 + 8) * SROW + kb + c + 4]);
            }
            uint32_t b[8][2];
#pragma unroll
            for (int nj = 0; nj < 8; nj++) {
                int n = warp_n * 64 + nj * 8 + g;
                b[nj][0] = to_tf32(Bs[n * SROW + kb + c]);
                b[nj][1] = to_tf32(Bs[n * SROW + kb + c + 4]);
            }
#pragma unroll
            for (int mi = 0; mi < 2; mi++)
#pragma unroll
                for (int nj = 0; nj < 8; nj++)
                    mma_tf32(acc[mi][nj][0], acc[mi][nj][1], acc[mi][nj][2], acc[mi][nj][3],
                             a[mi][0], a[mi][1], a[mi][2], a[mi][3],
                             b[nj][0], b[nj][1]);
        }
        __syncthreads();
        if (kt + 2 < KTC) load_stage(s, kt + 2);
    }

    // -------- epilogue --------
#pragma unroll
    for (int mi = 0; mi < 2; mi++) {
#pragma unroll
        for (int half = 0; half < 2; half++) {    // half 0: rows g (c0,c1); 1: rows g+8 (c2,c3)
            int mrow = m_base + warp_m * 32 + mi * 16 + g + half * 8;
            if (mrow >= cnt) continue;
            int slot = cl[mrow];
            if (MODE == 0) {
                float* dst = g_act + (size_t)slot * HID + bx * 64;
#pragma unroll
                for (int nj = 0; nj < 8; nj++) {
                    int hl = warp_n * 32 + nj * 4 + c;
                    float z0 = acc[mi][nj][half * 2];
                    float z1 = acc[mi][nj][half * 2 + 1];
                    dst[hl] = gelu_tanh(z0) * z1;
                }
            } else {
                float w = g_wt[e * NTOK + mrow];
                float* dst = g_part + (size_t)slot * DIM + bx * 128;
#pragma unroll
                for (int nj = 0; nj < 8; nj++) {
                    int col = warp_n * 64 + nj * 8 + c * 2;
                    dst[col]     = acc[mi][nj][half * 2] * w;
                    dst[col + 1] = acc[mi][nj][half * 2 + 1] * w;
                }
            }
        }
    }
}

// -------- kernel C: out[t][d] = part[2t][d] + part[2t+1][d] --------
__global__ void combine_kernel(float* __restrict__ out) {
    int idx = blockIdx.x * blockDim.x + threadIdx.x;
    if (idx >= NTOK * DIM / 4) return;
    int t = idx >> 8;
    int dc = (idx & 255) * 4;
    const float* p = g_part + (size_t)t * 2 * DIM + dc;
    float4 a = *(const float4*)p;
    float4 b = *(const float4*)(p + DIM);
    float4 r;
    r.x = a.x + b.x; r.y = a.y + b.y; r.z = a.z + b.z; r.w = a.w + b.w;
    *(float4*)(out + (size_t)t * DIM + dc) = r;
}

// -------- launcher --------
extern "C" void kernel_launch(void* const* d_in, const int* in_sizes, int n_in,
                              void* d_out, int out_size) {
    const float* x      = (const float*)d_in[0];
    const float* rscale = (const float*)d_in[1];
    const float* rw     = (const float*)d_in[2];
    const float* gw     = (const float*)d_in[3];
    const float* lw     = (const float*)d_in[4];
    const float* pes    = (const float*)d_in[5];
    float* out = (float*)d_out;

    const int smem = 4 * ASTG * 4;   // 73728 bytes
    cudaFuncSetAttribute(mma_gemm<0>, cudaFuncAttributeMaxDynamicSharedMemorySize, smem);
    cudaFuncSetAttribute(mma_gemm<1>, cudaFuncAttributeMaxDynamicSharedMemorySize, smem);

    zero_counts_kernel<<<1, 32>>>();
    transpose_kernel<<<dim3(DIM / 32, HID / 32, NEXP), dim3(32, 8)>>>(lw);
    router_kernel<<<NTOK, 256>>>(x, rscale, rw, pes);
    // up: bx covers 64 h (gate0+gate1 interleaved); fused GELU -> g_act
    mma_gemm<0><<<dim3(HID / 64, NTOK / 128, NEXP), 256, smem>>>(x, gw);
    // down: bx covers 128 d; weight-scaled -> g_part
    mma_gemm<1><<<dim3(DIM / 128, NTOK / 128, NEXP), 256, smem>>>(x, gw);
    combine_kernel<<<(NTOK * DIM / 4 + 255) / 256, 256>>>(out);
}